// round 1
// baseline (speedup 1.0000x reference)
#include <cuda_runtime.h>

#define BATCH 2
#define LSEQ 2048
#define HDIM 1024
#define NST 16
#define MROWS (BATCH*LSEQ)   // 4096
#define DT_MIN_V 0.001f
#define DT_MAX_V 0.02f

// Scratch (allocation-free rule: __device__ globals)
__device__ float g_dt [BATCH*LSEQ*HDIM];   // (B,L,H)
__device__ float g_dtT[BATCH*HDIM*LSEQ];   // (B,H,L)
__device__ float g_uT [BATCH*HDIM*LSEQ];   // (B,H,L)

typedef unsigned long long u64;

__device__ __forceinline__ u64 ffma2(u64 a, u64 b, u64 c){
    u64 d;
    asm("fma.rn.f32x2 %0, %1, %2, %3;" : "=l"(d) : "l"(a), "l"(b), "l"(c));
    return d;
}
__device__ __forceinline__ u64 pack2(float x){
    u64 d; unsigned r = __float_as_uint(x);
    asm("mov.b64 %0, {%1, %2};" : "=l"(d) : "r"(r), "r"(r));
    return d;
}

// ---------------------------------------------------------------------------
// GEMM: log_dt[m,g] = sum_k U[m,k]*W[g,k] + bias[g];  dt = clamp(exp(.))
// M=4096, N=1024, K=1024.  Block tile 128x128, BK=8, 256 threads, 8x8/thread,
// f32x2 packed accumulators (pairs along M), double-buffered smem.
// ---------------------------------------------------------------------------
__global__ __launch_bounds__(256) void gemm_dt_kernel(
        const float* __restrict__ U, const float* __restrict__ W,
        const float* __restrict__ bias){
    __shared__ float As[2][8][128];
    __shared__ float Bs[2][8][128];
    const int tid = threadIdx.x;
    const int bm = blockIdx.y * 128;
    const int bn = blockIdx.x * 128;
    const int lr = tid >> 1;          // 0..127 row within tile
    const int lk = (tid & 1) << 2;    // 0 or 4 (k offset)
    const float* aP = U + (size_t)(bm + lr) * 1024 + lk;
    const float* bP = W + (size_t)(bn + lr) * 1024 + lk;
    const int tx = tid & 15;
    const int ty = tid >> 4;

    u64 acc[4][8];
    #pragma unroll
    for (int i = 0; i < 4; i++)
        #pragma unroll
        for (int j = 0; j < 8; j++) acc[i][j] = 0ull;

    // preload k-tile 0
    float4 pa = *(const float4*)aP;
    float4 pb = *(const float4*)bP;
    #pragma unroll
    for (int i = 0; i < 4; i++){
        As[0][lk + i][lr] = ((const float*)&pa)[i];
        Bs[0][lk + i][lr] = ((const float*)&pb)[i];
    }
    __syncthreads();

    for (int kt = 0; kt < 128; kt++){
        const int cur = kt & 1;
        if (kt < 127){
            pa = *(const float4*)(aP + (kt + 1) * 8);
            pb = *(const float4*)(bP + (kt + 1) * 8);
        }
        #pragma unroll
        for (int k = 0; k < 8; k++){
            float4 av0 = *(const float4*)&As[cur][k][ty * 8];
            float4 av1 = *(const float4*)&As[cur][k][ty * 8 + 4];
            float4 bv0 = *(const float4*)&Bs[cur][k][tx * 8];
            float4 bv1 = *(const float4*)&Bs[cur][k][tx * 8 + 4];
            u64 a2[4];
            a2[0] = ((const u64*)&av0)[0];
            a2[1] = ((const u64*)&av0)[1];
            a2[2] = ((const u64*)&av1)[0];
            a2[3] = ((const u64*)&av1)[1];
            float bf[8] = {bv0.x, bv0.y, bv0.z, bv0.w, bv1.x, bv1.y, bv1.z, bv1.w};
            #pragma unroll
            for (int j = 0; j < 8; j++){
                u64 b2 = pack2(bf[j]);
                #pragma unroll
                for (int i = 0; i < 4; i++)
                    acc[i][j] = ffma2(a2[i], b2, acc[i][j]);
            }
        }
        if (kt < 127){
            const int nxt = cur ^ 1;
            #pragma unroll
            for (int i = 0; i < 4; i++){
                As[nxt][lk + i][lr] = ((const float*)&pa)[i];
                Bs[nxt][lk + i][lr] = ((const float*)&pb)[i];
            }
            __syncthreads();
        }
    }

    // Epilogue: bias + exp + clamp, store dt (B,L,H) = [m, g]
    const int gbase = bn + tx * 8;
    float bvals[8];
    #pragma unroll
    for (int j = 0; j < 8; j++) bvals[j] = bias[gbase + j];
    #pragma unroll
    for (int i = 0; i < 4; i++){
        #pragma unroll
        for (int p = 0; p < 2; p++){
            const int m = bm + ty * 8 + i * 2 + p;
            float o[8];
            #pragma unroll
            for (int j = 0; j < 8; j++){
                float v = ((const float*)&acc[i][j])[p] + bvals[j];
                v = __expf(v);
                o[j] = fminf(fmaxf(v, DT_MIN_V), DT_MAX_V);
            }
            float4* dst = (float4*)&g_dt[(size_t)m * 1024 + gbase];
            dst[0] = make_float4(o[0], o[1], o[2], o[3]);
            dst[1] = make_float4(o[4], o[5], o[6], o[7]);
        }
    }
}

// ---------------------------------------------------------------------------
// Transpose (B,L,H) -> (B,H,L) for both u and dt. grid.z: 0..1 = u(b), 2..3 = dt(b)
// ---------------------------------------------------------------------------
__global__ void transpose_kernel(const float* __restrict__ u){
    __shared__ float tile[32][33];
    const int z = blockIdx.z;
    const float* src; float* dst;
    if (z < BATCH){
        src = u    + (size_t)z * LSEQ * HDIM;
        dst = g_uT + (size_t)z * HDIM * LSEQ;
    } else {
        const int b = z - BATCH;
        src = g_dt  + (size_t)b * LSEQ * HDIM;
        dst = g_dtT + (size_t)b * HDIM * LSEQ;
    }
    const int h0 = blockIdx.x * 32;
    const int l0 = blockIdx.y * 32;
    const int tx = threadIdx.x, ty = threadIdx.y;
    #pragma unroll
    for (int i = 0; i < 32; i += 8)
        tile[ty + i][tx] = src[(size_t)(l0 + ty + i) * HDIM + h0 + tx];
    __syncthreads();
    #pragma unroll
    for (int i = 0; i < 32; i += 8)
        dst[(size_t)(h0 + ty + i) * LSEQ + l0 + tx] = tile[tx][ty + i];
}

// ---------------------------------------------------------------------------
// Scan: each 16-lane group = one (b,h) channel, lane = state index n.
//   x = x*exp(dt*A) + ((exp(dt*A)-1)/A)*B*u ;  y = sum_n x*C + D*u
// Block = 256 thr = 16 channels (16 consecutive h, same b). Output staged
// through smem 16x16 tile for coalesced (B,L,H) stores.
// ---------------------------------------------------------------------------
__global__ __launch_bounds__(256) void scan_kernel(
        const float* __restrict__ Alog, const float* __restrict__ Bp,
        const float* __restrict__ Cp, const float* __restrict__ Dp,
        float* __restrict__ out){
    __shared__ float ytile[16][17];
    const int tid = threadIdx.x;
    const int n = tid & 15;
    const int grp = tid >> 4;              // 0..15
    const int sbase = blockIdx.x * 16;
    const int s = sbase + grp;             // channel id in [0, 2048)
    const int b = s >> 10;
    const int h = s & 1023;
    const int h0 = sbase & 1023;

    const float A    = -expf(Alog[h * NST + n]);   // exactly -exp(A_log)
    const float invA = 1.0f / A;
    const float BinvA = Bp[h * NST + n] * invA;
    const float Cn   = Cp[h * NST + n];
    const float Dh   = Dp[h];
    const float Al2  = A * 1.4426950408889634f;    // A * log2(e) for ex2

    const float* dtp = g_dtT + (size_t)(b * HDIM + h) * LSEQ;
    const float* up  = g_uT  + (size_t)(b * HDIM + h) * LSEQ;
    float* outp = out + (size_t)b * LSEQ * HDIM + h0;

    float x = 0.0f;
    for (int l0 = 0; l0 < LSEQ; l0 += 16){
        #pragma unroll
        for (int t = 0; t < 16; t++){
            const int l = l0 + t;
            const float dt = __ldg(dtp + l);
            const float uu = __ldg(up + l);
            const float zl2 = dt * Al2;
            float abar;
            asm("ex2.approx.f32 %0, %1;" : "=f"(abar) : "f"(zl2));
            const float t1 = BinvA * uu;
            const float bu = fmaf(abar, t1, -t1);   // (abar-1)*B/A*u
            x = fmaf(x, abar, bu);
            float v = x * Cn;
            v += __shfl_xor_sync(0xffffffffu, v, 1);
            v += __shfl_xor_sync(0xffffffffu, v, 2);
            v += __shfl_xor_sync(0xffffffffu, v, 4);
            v += __shfl_xor_sync(0xffffffffu, v, 8);
            if (n == t) ytile[t][grp] = fmaf(Dh, uu, v);
        }
        __syncthreads();
        {
            const int lw = tid >> 4;   // local l
            const int hw = tid & 15;   // local h
            outp[(size_t)(l0 + lw) * HDIM + hw] = ytile[lw][hw];
        }
        __syncthreads();
    }
}

// ---------------------------------------------------------------------------
extern "C" void kernel_launch(void* const* d_in, const int* in_sizes, int n_in,
                              void* d_out, int out_size){
    const float* u    = (const float*)d_in[0];
    const float* Alog = (const float*)d_in[1];
    const float* Bp   = (const float*)d_in[2];
    const float* Cp   = (const float*)d_in[3];
    const float* Dp   = (const float*)d_in[4];
    const float* Wdt  = (const float*)d_in[5];
    const float* bdt  = (const float*)d_in[6];
    float* out = (float*)d_out;

    dim3 ggrid(HDIM / 128, MROWS / 128);           // (8, 32)
    gemm_dt_kernel<<<ggrid, 256>>>(u, Wdt, bdt);

    dim3 tgrid(HDIM / 32, LSEQ / 32, 2 * BATCH);   // (32, 64, 4)
    transpose_kernel<<<tgrid, dim3(32, 8)>>>(u);

    scan_kernel<<<BATCH * HDIM / 16, 256>>>(Alog, Bp, Cp, Dp, out);
}

// round 2
// speedup vs baseline: 2.4231x; 2.4231x over previous
#include <cuda_runtime.h>

#define BATCH 2
#define LSEQ 2048
#define HDIM 1024
#define NST 16
#define MROWS (BATCH*LSEQ)     // 4096
#define DT_MIN_V 0.001f
#define DT_MAX_V 0.02f
#define NCHUNK 8
#define CHLEN (LSEQ/NCHUNK)    // 256
#define NCH (BATCH*HDIM)       // 2048
#define LOG2E 1.4426950408889634f

// Scratch (__device__ globals: allocation-free rule)
__device__ float g_dtT[BATCH*HDIM*LSEQ];       // (B,H,L)
__device__ float g_uT [BATCH*HDIM*LSEQ];       // (B,H,L)
__device__ float g_P  [NCHUNK*NCH*NST];        // per-chunk prod(abar)
__device__ float g_S  [NCHUNK*NCH*NST];        // per-chunk local end state
__device__ float g_Xin[NCHUNK*NCH*NST];        // per-chunk initial state

// ---------------------------------------------------------------------------
// TF32 tensor-core GEMM: log_dt[m,g] = sum_k U[m,k]*W[g,k] + b[g]
// dt = clamp(exp(log_dt));  writes g_dtT[(b,g,l)] directly (fused transpose).
// M=4096, N=1024, K=1024. Block 128x128, BK=32, 8 warps (warp tile 64x32),
// cp.async double-buffered, XOR-swizzled smem, ldmatrix fragment loads.
// ---------------------------------------------------------------------------
__device__ __forceinline__ void cp16(float* s, const float* g){
    unsigned sa = (unsigned)__cvta_generic_to_shared(s);
    asm volatile("cp.async.cg.shared.global [%0], [%1], 16;" :: "r"(sa), "l"(g));
}
__device__ __forceinline__ void ldsm4(unsigned* r, unsigned addr){
    asm volatile("ldmatrix.sync.aligned.m8n8.x4.shared.b16 {%0,%1,%2,%3}, [%4];"
        : "=r"(r[0]), "=r"(r[1]), "=r"(r[2]), "=r"(r[3]) : "r"(addr));
}
__device__ __forceinline__ void mma_tf32(float* d, const unsigned* a,
                                         unsigned b0, unsigned b1){
    asm volatile(
        "mma.sync.aligned.m16n8k8.row.col.f32.tf32.tf32.f32 "
        "{%0,%1,%2,%3}, {%4,%5,%6,%7}, {%8,%9}, {%0,%1,%2,%3};"
        : "+f"(d[0]), "+f"(d[1]), "+f"(d[2]), "+f"(d[3])
        : "r"(a[0]), "r"(a[1]), "r"(a[2]), "r"(a[3]), "r"(b0), "r"(b1));
}

__global__ __launch_bounds__(256) void gemm_tf32_kernel(
        const float* __restrict__ U, const float* __restrict__ W,
        const float* __restrict__ bias){
    extern __shared__ float smem[];       // 2 stages x (4096 A + 4096 B) floats
    const int tid  = threadIdx.x;
    const int lane = tid & 31;
    const int wid  = tid >> 5;
    const int wm   = wid & 1;             // 2 warps along M (64 each)
    const int wn   = wid >> 1;            // 4 warps along N (32 each)
    const int bm   = blockIdx.y * 128;
    const int bn   = blockIdx.x * 128;

    float acc[4][4][4];
    #pragma unroll
    for (int i = 0; i < 4; i++)
        #pragma unroll
        for (int j = 0; j < 4; j++)
            #pragma unroll
            for (int r = 0; r < 4; r++) acc[i][j][r] = 0.f;

    const int lrow = tid >> 3;            // 0..31
    const int lkc  = tid & 7;             // 16B chunk in row

    // fragment smem byte-address components (stage 0 base)
    unsigned smemBase = (unsigned)__cvta_generic_to_shared(smem);
    const unsigned aRowOff = (unsigned)((wm * 64 + (lane & 15)) * 128);
    const unsigned bRowOff = (unsigned)((wn * 32 + ((lane & 16) >> 1) + (lane & 7)) * 128);
    int physA[4], physB[4];
    #pragma unroll
    for (int ks = 0; ks < 4; ks++){
        physA[ks] = ((2 * ks + (lane >> 4)) ^ (lane & 7)) * 16;
        physB[ks] = ((2 * ks + ((lane >> 3) & 1)) ^ (lane & 7)) * 16;
    }

    // ---- loader lambda (manually inlined twice) ----
    #define LOAD_TILE(KT, STG) do {                                            \
        float* A_s = smem + (STG) * 8192;                                      \
        float* B_s = A_s + 4096;                                               \
        _Pragma("unroll")                                                      \
        for (int i = 0; i < 4; i++){                                           \
            int row  = lrow + i * 32;                                          \
            int phys = lkc ^ (row & 7);                                        \
            cp16(A_s + row * 32 + phys * 4,                                    \
                 U + (size_t)(bm + row) * 1024 + (KT) * 32 + lkc * 4);         \
            cp16(B_s + row * 32 + phys * 4,                                    \
                 W + (size_t)(bn + row) * 1024 + (KT) * 32 + lkc * 4);         \
        }                                                                      \
        asm volatile("cp.async.commit_group;");                                \
    } while (0)

    LOAD_TILE(0, 0);

    for (int kt = 0; kt < 32; kt++){
        const int cur = kt & 1;
        if (kt < 31) LOAD_TILE(kt + 1, cur ^ 1);
        if (kt < 31) asm volatile("cp.async.wait_group 1;");
        else         asm volatile("cp.async.wait_group 0;");
        __syncthreads();

        unsigned aB = smemBase + cur * 32768 + aRowOff;
        unsigned bB = smemBase + cur * 32768 + 16384 + bRowOff;
        #pragma unroll
        for (int ks = 0; ks < 4; ks++){
            unsigned a[4][4], bb[2][4];
            #pragma unroll
            for (int mt = 0; mt < 4; mt++)
                ldsm4(a[mt], aB + mt * 16 * 128 + physA[ks]);
            #pragma unroll
            for (int tp = 0; tp < 2; tp++)
                ldsm4(bb[tp], bB + tp * 16 * 128 + physB[ks]);
            #pragma unroll
            for (int mt = 0; mt < 4; mt++)
                #pragma unroll
                for (int nt = 0; nt < 4; nt++)
                    mma_tf32(acc[mt][nt], a[mt],
                             bb[nt >> 1][(nt & 1) * 2], bb[nt >> 1][(nt & 1) * 2 + 1]);
        }
        __syncthreads();
    }

    // Epilogue: bias + exp + clamp, write transposed directly: dtT[b][g][l]
    const int rbase = bm + wm * 64 + (lane >> 2);
    const int gbase = bn + wn * 32 + 2 * (lane & 3);
    float bv[4][2];
    #pragma unroll
    for (int nt = 0; nt < 4; nt++){
        bv[nt][0] = __ldg(bias + gbase + nt * 8);
        bv[nt][1] = __ldg(bias + gbase + nt * 8 + 1);
    }
    #pragma unroll
    for (int mt = 0; mt < 4; mt++)
        #pragma unroll
        for (int nt = 0; nt < 4; nt++)
            #pragma unroll
            for (int r = 0; r < 4; r++){
                const int m = rbase + mt * 16 + ((r >= 2) ? 8 : 0);
                const int g = gbase + nt * 8 + (r & 1);
                float v = acc[mt][nt][r] + bv[nt][r & 1];
                v = __expf(v);
                v = fminf(fmaxf(v, DT_MIN_V), DT_MAX_V);
                const int b = m >> 11, l = m & 2047;
                g_dtT[((size_t)b * HDIM + g) * LSEQ + l] = v;
            }
}

// ---------------------------------------------------------------------------
// Transpose u: (B,L,H) -> (B,H,L)
// ---------------------------------------------------------------------------
__global__ void transpose_kernel(const float* __restrict__ u){
    __shared__ float tile[32][33];
    const int b = blockIdx.z;
    const float* src = u    + (size_t)b * LSEQ * HDIM;
    float*       dst = g_uT + (size_t)b * HDIM * LSEQ;
    const int h0 = blockIdx.x * 32;
    const int l0 = blockIdx.y * 32;
    const int tx = threadIdx.x, ty = threadIdx.y;
    #pragma unroll
    for (int i = 0; i < 32; i += 8)
        tile[ty + i][tx] = src[(size_t)(l0 + ty + i) * HDIM + h0 + tx];
    __syncthreads();
    #pragma unroll
    for (int i = 0; i < 32; i += 8)
        dst[(size_t)(h0 + ty + i) * LSEQ + l0 + tx] = tile[tx][ty + i];
}

// ---------------------------------------------------------------------------
// Pass 1: per-(channel,chunk) reduce -> P = prod(abar), S = local end state
// 16 lanes per work item (lane = state n). 16 items per block of 256.
// ---------------------------------------------------------------------------
__global__ __launch_bounds__(256) void scan_reduce_kernel(
        const float* __restrict__ Alog, const float* __restrict__ Bp){
    const int tid = threadIdx.x;
    const int n   = tid & 15;
    const int grp = tid >> 4;
    const int p   = blockIdx.x * 16 + grp;     // 0..16383
    const int ch    = p & (NCH - 1);
    const int chunk = p >> 11;
    const int b = ch >> 10, h = ch & 1023;

    const float A     = -expf(Alog[h * NST + n]);
    const float Al2   = A * LOG2E;
    const float BinvA = Bp[h * NST + n] / A;

    const float* dtp = g_dtT + (size_t)(b * HDIM + h) * LSEQ + chunk * CHLEN;
    const float* up  = g_uT  + (size_t)(b * HDIM + h) * LSEQ + chunk * CHLEN;

    float x = 0.f, P = 1.f;
    #pragma unroll 8
    for (int l = 0; l < CHLEN; l++){
        const float dt = __ldg(dtp + l);
        const float uu = __ldg(up + l);
        float abar;
        asm("ex2.approx.f32 %0, %1;" : "=f"(abar) : "f"(dt * Al2));
        const float t1 = BinvA * uu;
        const float bu = fmaf(abar, t1, -t1);
        x = fmaf(x, abar, bu);
        P *= abar;
    }
    g_P[(size_t)p * NST + n] = P;
    g_S[(size_t)p * NST + n] = x;
}

// ---------------------------------------------------------------------------
// Pass 2: stitch chunk boundary states serially (tiny). thread = (channel,n)
// ---------------------------------------------------------------------------
__global__ void scan_stitch_kernel(){
    const int id = blockIdx.x * blockDim.x + threadIdx.x;  // 0..32767
    const int ch = id >> 4, n = id & 15;
    float x = 0.f;
    #pragma unroll
    for (int c = 0; c < NCHUNK; c++){
        const size_t idx = ((size_t)c * NCH + ch) * NST + n;
        g_Xin[idx] = x;
        x = g_P[idx] * x + g_S[idx];
    }
}

// ---------------------------------------------------------------------------
// Pass 3: full scan within each chunk starting from g_Xin; emits y.
// Block = 16 channels (contiguous h, same b), one chunk. Output staged in
// smem 16x16 for coalesced (B,L,H) stores.
// ---------------------------------------------------------------------------
__global__ __launch_bounds__(256) void scan_final_kernel(
        const float* __restrict__ Alog, const float* __restrict__ Bp,
        const float* __restrict__ Cp, const float* __restrict__ Dp,
        float* __restrict__ out){
    __shared__ float ytile[16][17];
    const int tid = threadIdx.x;
    const int n   = tid & 15;
    const int grp = tid >> 4;
    const int sbase = blockIdx.x * 16;
    const int s = sbase + grp;                 // channel 0..2047
    const int chunk = blockIdx.y;
    const int b = s >> 10;
    const int h = s & 1023;
    const int h0 = sbase & 1023;

    const float A     = -expf(Alog[h * NST + n]);
    const float Al2   = A * LOG2E;
    const float BinvA = Bp[h * NST + n] / A;
    const float Cn    = Cp[h * NST + n];
    const float Dh    = Dp[h];

    const float* dtp = g_dtT + (size_t)(b * HDIM + h) * LSEQ;
    const float* up  = g_uT  + (size_t)(b * HDIM + h) * LSEQ;
    float* outp = out + (size_t)b * LSEQ * HDIM + h0;

    float x = g_Xin[((size_t)chunk * NCH + s) * NST + n];

    const int lbeg = chunk * CHLEN;
    for (int l0 = lbeg; l0 < lbeg + CHLEN; l0 += 16){
        #pragma unroll
        for (int t = 0; t < 16; t++){
            const int l = l0 + t;
            const float dt = __ldg(dtp + l);
            const float uu = __ldg(up + l);
            float abar;
            asm("ex2.approx.f32 %0, %1;" : "=f"(abar) : "f"(dt * Al2));
            const float t1 = BinvA * uu;
            const float bu = fmaf(abar, t1, -t1);
            x = fmaf(x, abar, bu);
            float v = x * Cn;
            v += __shfl_xor_sync(0xffffffffu, v, 1);
            v += __shfl_xor_sync(0xffffffffu, v, 2);
            v += __shfl_xor_sync(0xffffffffu, v, 4);
            v += __shfl_xor_sync(0xffffffffu, v, 8);
            if (n == t) ytile[t][grp] = fmaf(Dh, uu, v);
        }
        __syncthreads();
        {
            const int lw = tid >> 4;
            const int hw = tid & 15;
            outp[(size_t)(l0 + lw) * HDIM + hw] = ytile[lw][hw];
        }
        __syncthreads();
    }
}

// ---------------------------------------------------------------------------
extern "C" void kernel_launch(void* const* d_in, const int* in_sizes, int n_in,
                              void* d_out, int out_size){
    const float* u    = (const float*)d_in[0];
    const float* Alog = (const float*)d_in[1];
    const float* Bp   = (const float*)d_in[2];
    const float* Cp   = (const float*)d_in[3];
    const float* Dp   = (const float*)d_in[4];
    const float* Wdt  = (const float*)d_in[5];
    const float* bdt  = (const float*)d_in[6];
    float* out = (float*)d_out;

    cudaFuncSetAttribute(gemm_tf32_kernel,
                         cudaFuncAttributeMaxDynamicSharedMemorySize, 65536);

    dim3 ggrid(HDIM / 128, MROWS / 128);            // (8, 32)
    gemm_tf32_kernel<<<ggrid, 256, 65536>>>(u, Wdt, bdt);

    dim3 tgrid(HDIM / 32, LSEQ / 32, BATCH);
    transpose_kernel<<<tgrid, dim3(32, 8)>>>(u);

    scan_reduce_kernel<<<NCHUNK * NCH / 16, 256>>>(Alog, Bp);
    scan_stitch_kernel<<<NCH * NST / 256, 256>>>();
    scan_final_kernel<<<dim3(NCH / 16, NCHUNK), 256>>>(Alog, Bp, Cp, Dp, out);
}